// round 11
// baseline (speedup 1.0000x reference)
#include <cuda_runtime.h>
#include <cuda_bf16.h>

#define ROWS 4096
#define COLS 32000
#define NF4  (COLS / 4)                  // 8000 float4 per row
#define WORDS (COLS / 32)                // 1000 bitmask words per row
#define CAP  3072                        // compacted tail capacity (expected ~1200)
#define BD   256                         // block dim
#define VPT  2                           // float4 per thread per chunk (K1)
#define CHW  (BD * VPT)                  // float4 per chunk = 512
#define NCHUNK ((NF4 + CHW - 1) / CHW)   // 16 chunks
#define NEG_INF (-3.402823466e38f)

// ---- global scratch (device globals: allowed; no runtime allocation) ----
__device__ float g_vals[(size_t)ROWS * CAP];
__device__ int   g_gidx[(size_t)ROWS * CAP];
__device__ float g_max[ROWS];
__device__ int   g_cnt[ROWS];

// Monotone float<->uint mapping for atomicMax on floats (any sign).
__device__ __forceinline__ unsigned fenc(float f) {
    unsigned b = __float_as_uint(f);
    return b ^ ((unsigned)((int)b >> 31) | 0x80000000u);
}
__device__ __forceinline__ float fdec(unsigned u) {
    unsigned b = u ^ ((u & 0x80000000u) ? 0x80000000u : 0xFFFFFFFFu);
    return __uint_as_float(b);
}

// ===========================================================================
// K1: pure-read streaming. Barrier-free running block max; superset filter at
// (runmax*0.5 - 1); kept (val,idx) pairs go straight to global scratch.
// ===========================================================================
__global__ __launch_bounds__(BD, 8) void k1_compact(const float* __restrict__ X) {
    const int row = blockIdx.x;
    const float4* Xr = reinterpret_cast<const float4*>(X + (size_t)row * COLS);
    float* gv = g_vals + (size_t)row * CAP;
    int*   gx = g_gidx + (size_t)row * CAP;

    __shared__ unsigned s_maxu;
    __shared__ int      s_count;

    const int tid  = threadIdx.x;
    const int lane = tid & 31;

    if (tid == 0) { s_maxu = fenc(NEG_INF); s_count = 0; }
    __syncthreads();

    const float4 neg4 = make_float4(NEG_INF, NEG_INF, NEG_INF, NEG_INF);

    // chunk 0 (fully in-bounds): seed block max with one barrier
    float4 v0 = __ldcs(&Xr[tid]);
    float4 v1 = __ldcs(&Xr[tid + BD]);
    float4 p0 = __ldcs(&Xr[tid + CHW]);
    float4 p1 = __ldcs(&Xr[tid + CHW + BD]);
    {
        float tm = fmaxf(fmaxf(fmaxf(v0.x, v0.y), fmaxf(v0.z, v0.w)),
                         fmaxf(fmaxf(v1.x, v1.y), fmaxf(v1.z, v1.w)));
        #pragma unroll
        for (int o = 16; o > 0; o >>= 1)
            tm = fmaxf(tm, __shfl_xor_sync(0xFFFFFFFFu, tm, o));
        if (lane == 0) atomicMax(&s_maxu, fenc(tm));
        __syncthreads();
        const float thresh = fdec(s_maxu) * 0.5f - 1.0f;
        if (tm * 0.5f > thresh) {
            const float xs[8] = {v0.x * 0.5f, v0.y * 0.5f, v0.z * 0.5f, v0.w * 0.5f,
                                 v1.x * 0.5f, v1.y * 0.5f, v1.z * 0.5f, v1.w * 0.5f};
            #pragma unroll
            for (int k = 0; k < 8; k++) {
                const int gi = (((k < 4) ? tid : tid + BD)) * 4 + (k & 3);
                const bool p = (xs[k] > thresh);
                const unsigned mask = __ballot_sync(0xFFFFFFFFu, p);
                if (mask == 0u) continue;
                if (p) {
                    const int rank   = __popc(mask & ((1u << lane) - 1u));
                    const int leader = __ffs(mask) - 1;
                    int base = 0;
                    if (lane == leader) base = atomicAdd(&s_count, __popc(mask));
                    base = __shfl_sync(mask, base, leader);
                    const int idx = base + rank;
                    if (idx < CAP) { gv[idx] = xs[k]; gx[idx] = gi; }
                }
            }
        }
    }

    // chunks 1..15: barrier-free, prefetched stream
    #pragma unroll 1
    for (int c = 1; c < NCHUNK; c++) {
        const int base0 = c * CHW + tid;
        const int base1 = base0 + BD;
        const bool val0 = (base0 < NF4);
        const bool val1 = (base1 < NF4);
        float4 w0 = p0, w1 = p1;
        p0 = neg4; p1 = neg4;
        if (c + 1 < NCHUNK) {
            const int b0 = base0 + CHW, b1 = base1 + CHW;
            if (b0 < NF4) p0 = __ldcs(&Xr[b0]);
            if (b1 < NF4) p1 = __ldcs(&Xr[b1]);
        }
        if (!val0) w0 = neg4;
        if (!val1) w1 = neg4;

        float tm = fmaxf(fmaxf(fmaxf(w0.x, w0.y), fmaxf(w0.z, w0.w)),
                         fmaxf(fmaxf(w1.x, w1.y), fmaxf(w1.z, w1.w)));
        #pragma unroll
        for (int o = 16; o > 0; o >>= 1)
            tm = fmaxf(tm, __shfl_xor_sync(0xFFFFFFFFu, tm, o));
        unsigned old = 0;
        if (lane == 0) old = atomicMax(&s_maxu, fenc(tm));
        old = __shfl_sync(0xFFFFFFFFu, old, 0);
        const float m = fmaxf(fdec(old), tm);
        const float thresh = m * 0.5f - 1.0f;          // <= final thresh => superset

        if (tm * 0.5f > thresh) {                      // warp-uniform skip
            const float xs[8] = {w0.x * 0.5f, w0.y * 0.5f, w0.z * 0.5f, w0.w * 0.5f,
                                 w1.x * 0.5f, w1.y * 0.5f, w1.z * 0.5f, w1.w * 0.5f};
            #pragma unroll
            for (int k = 0; k < 8; k++) {
                const bool vk = (k < 4) ? val0 : val1;
                const int  gi = ((k < 4) ? base0 : base1) * 4 + (k & 3);
                const bool p  = vk && (xs[k] > thresh);
                const unsigned mask = __ballot_sync(0xFFFFFFFFu, p);
                if (mask == 0u) continue;
                if (p) {
                    const int rank   = __popc(mask & ((1u << lane) - 1u));
                    const int leader = __ffs(mask) - 1;
                    int base = 0;
                    if (lane == leader) base = atomicAdd(&s_count, __popc(mask));
                    base = __shfl_sync(mask, base, leader);
                    const int idx = base + rank;
                    if (idx < CAP) { gv[idx] = xs[k]; gx[idx] = gi; }
                }
            }
        }
    }
    __syncthreads();
    if (tid == 0) { g_max[row] = fdec(s_maxu); g_cnt[row] = s_count; }
}

// ===========================================================================
// K2: pure-write streaming. Bitmask + prefix ranks; warp 0 bisects while
// warps 1-7 write zero quads; then dense p-values and mixed quads. Every
// output float4 written exactly once, fully coalesced. No RMW.
// ===========================================================================
__global__ __launch_bounds__(BD) void k2_write(const float* __restrict__ X,
                                               float* __restrict__ out) {
    const int row = blockIdx.x;
    float4* Or = reinterpret_cast<float4*>(out + (size_t)row * COLS);

    __shared__ float    s_val[CAP];
    __shared__ int      s_sidx[CAP];
    __shared__ float    s_pval[CAP];
    __shared__ unsigned s_bits[WORDS];
    __shared__ int      s_pref[WORDS];
    __shared__ int      s_wsum[8];
    __shared__ float    s_tau, s_invZ;

    const int tid  = threadIdx.x;
    const int lane = tid & 31;
    const int wrp  = tid >> 5;

    const int   cnt   = g_cnt[row];
    const float max_s = g_max[row] * 0.5f;
    const int   n     = (cnt < CAP) ? cnt : CAP;
    const bool  ovf   = (cnt > CAP);
    const float* gv = g_vals + (size_t)row * CAP;
    const int*   gx = g_gidx + (size_t)row * CAP;

    if (!ovf) {
        // load pairs, clear bitmask
        for (int j = tid; j < n; j += BD) { s_val[j] = gv[j]; s_sidx[j] = gx[j]; }
        for (int w = tid; w < WORDS; w += BD) s_bits[w] = 0u;
        __syncthreads();
        for (int j = tid; j < n; j += BD) {
            const int gi = s_sidx[j];
            atomicOr(&s_bits[gi >> 5], 1u << (gi & 31));
        }
        __syncthreads();

        // exclusive prefix of per-word popcounts (256 thr x 4 words = 1024 >= 1000)
        const int t4 = tid * 4;
        int pc[4]; int run = 0;
        #pragma unroll
        for (int k = 0; k < 4; k++) {
            const int w = t4 + k;
            const int c = (w < WORDS) ? __popc(s_bits[w]) : 0;
            pc[k] = run; run += c;
        }
        int tot = run;
        #pragma unroll
        for (int o = 1; o < 32; o <<= 1) {
            int v = __shfl_up_sync(0xFFFFFFFFu, tot, o);
            if (lane >= o) tot += v;
        }
        const int thr_excl = tot - run;
        if (lane == 31) s_wsum[wrp] = tot;
        __syncthreads();
        if (wrp == 0 && lane < 8) {
            int v = s_wsum[lane];
            int t = v;
            #pragma unroll
            for (int o = 1; o < 8; o <<= 1) {
                int u = __shfl_up_sync(0x000000FFu, t, o);
                if (lane >= o) t += u;
            }
            s_wsum[lane] = t - v;    // exclusive warp offset
        }
        __syncthreads();
        const int base = s_wsum[wrp] + thr_excl;
        #pragma unroll
        for (int k = 0; k < 4; k++)
            if (t4 + k < WORDS) s_pref[t4 + k] = base + pc[k];
        __syncthreads();

        // warp 0: 50-iter bisection; warps 1-7: write all-zero quads (tau-free)
        if (wrp == 0) {
            float tau_lo = max_s - 1.0f;
            const float tau_hi = max_s - 0.005590169943749474f;
            float dm = tau_hi - tau_lo;
            float tau_m = tau_lo;
            float Z = 1.0f;
            #pragma unroll 1
            for (int it = 0; it < 50; it++) {
                dm *= 0.5f;
                tau_m = tau_lo + dm;
                float acc = 0.0f;
                #pragma unroll 8
                for (int j = lane; j < n; j += 32) {
                    float t = fmaxf(s_val[j] - tau_m, 0.0f);
                    acc = fmaf(t, t, acc);
                }
                #pragma unroll
                for (int o = 16; o > 0; o >>= 1)
                    acc += __shfl_xor_sync(0xFFFFFFFFu, acc, o);
                if (acc - 1.0f >= 0.0f) tau_lo = tau_m;
                Z = acc;
            }
            if (lane == 0) { s_tau = tau_m; s_invZ = 1.0f / Z; }
        } else {
            const float4 z4 = make_float4(0.0f, 0.0f, 0.0f, 0.0f);
            for (int q = tid - 32; q < NF4; q += BD - 32) {
                const unsigned nib = (s_bits[q >> 3] >> ((q & 7) * 4)) & 0xFu;
                if (nib == 0u) __stcs(&Or[q], z4);
            }
        }
        __syncthreads();

        const float tau  = s_tau;
        const float invZ = s_invZ;

        // dense p-values by rank
        for (int j = tid; j < n; j += BD) {
            const int gi = s_sidx[j];
            const unsigned wm = s_bits[gi >> 5];
            const int rank = s_pref[gi >> 5] + __popc(wm & ((1u << (gi & 31)) - 1u));
            const float t = fmaxf(s_val[j] - tau, 0.0f);
            s_pval[rank] = t * t * invZ;
        }
        __syncthreads();

        // mixed quads: compose in registers, single coalesced store
        for (int q = tid; q < NF4; q += BD) {
            const unsigned word = s_bits[q >> 3];
            const int shift = (q & 7) * 4;
            const unsigned nib = (word >> shift) & 0xFu;
            if (nib != 0u) {
                const unsigned below = shift ? (word & ((1u << shift) - 1u)) : 0u;
                int r = s_pref[q >> 3] + __popc(below);
                float4 o;
                o.x = (nib & 1u) ? s_pval[r++] : 0.0f;
                o.y = (nib & 2u) ? s_pval[r++] : 0.0f;
                o.z = (nib & 4u) ? s_pval[r++] : 0.0f;
                o.w = (nib & 8u) ? s_pval[r++] : 0.0f;
                __stcs(&Or[q], o);
            }
        }
    } else {
        // exact full-row fallback (practically never taken)
        const float* Xrow = X + (size_t)row * COLS;
        if (wrp == 0) {
            float tau_lo = max_s - 1.0f;
            const float tau_hi = max_s - 0.005590169943749474f;
            float dm = tau_hi - tau_lo;
            float tau_m = tau_lo;
            float Z = 1.0f;
            #pragma unroll 1
            for (int it = 0; it < 50; it++) {
                dm *= 0.5f;
                tau_m = tau_lo + dm;
                float acc = 0.0f;
                for (int j = lane; j < COLS; j += 32) {
                    float t = fmaxf(fmaf(Xrow[j], 0.5f, -tau_m), 0.0f);
                    acc = fmaf(t, t, acc);
                }
                #pragma unroll
                for (int o = 16; o > 0; o >>= 1)
                    acc += __shfl_xor_sync(0xFFFFFFFFu, acc, o);
                if (acc - 1.0f >= 0.0f) tau_lo = tau_m;
                Z = acc;
            }
            if (lane == 0) { s_tau = tau_m; s_invZ = 1.0f / Z; }
        }
        __syncthreads();
        const float tau = s_tau, invZ = s_invZ;
        const float4* Xr4 = reinterpret_cast<const float4*>(Xrow);
        for (int i = tid; i < NF4; i += BD) {
            float4 xv = Xr4[i];
            float4 o; float t;
            t = fmaxf(xv.x * 0.5f - tau, 0.0f); o.x = t * t * invZ;
            t = fmaxf(xv.y * 0.5f - tau, 0.0f); o.y = t * t * invZ;
            t = fmaxf(xv.z * 0.5f - tau, 0.0f); o.z = t * t * invZ;
            t = fmaxf(xv.w * 0.5f - tau, 0.0f); o.w = t * t * invZ;
            Or[i] = o;
        }
    }
}

// ---------------------------------------------------------------------------
extern "C" void kernel_launch(void* const* d_in, const int* in_sizes, int n_in,
                              void* d_out, int out_size) {
    const float* X = (const float*)d_in[0];
    float* out = (float*)d_out;
    k1_compact<<<ROWS, BD>>>(X);
    k2_write<<<ROWS, BD>>>(X, out);
}